// round 16
// baseline (speedup 1.0000x reference)
#include <cuda_runtime.h>

#define B_ 8
#define P_ 10
#define S_ 160
#define FX_ 11
#define D_ 64
#define DFF_ 256
#define NROW (B_*P_*S_)   /* 12800 */
#define NPART (B_*P_)     /* 80 */

/* output layout (tuple order): pred, pred_resampl, K, V, R, attn_weights */
#define OFF_PRED  0
#define OFF_PRED2 (NROW)
#define OFF_K     (2*NROW)
#define OFF_V     (OFF_K + NROW*D_)
#define OFF_R     (OFF_V + NROW*D_)
#define OFF_ATTN  (OFF_R + NROW*D_)

/* scratch (no cudaMalloc allowed) */
__device__ float g_x[NROW*D_];
__device__ float g_q[NROW*D_];
__device__ float g_z[NROW*D_];

__device__ __forceinline__ void fma4(float4& acc, float s, const float4& v) {
    acc.x += s * v.x; acc.y += s * v.y; acc.z += s * v.z; acc.w += s * v.w;
}

/* ------------------------------------------------------------------ */
/* K1: in-block fold (single-pass) + x,q,k,v = in @ fused.            */
/* 200 blocks x 512 thr x 64 rows. Attention scale 1/8 folded in q.   */
/* ------------------------------------------------------------------ */
__global__ void __launch_bounds__(512) k_qkv(
    const float* __restrict__ inp,
    const float* __restrict__ Wp, const float* __restrict__ bp,
    const float* __restrict__ Wq, const float* __restrict__ bq,
    const float* __restrict__ Wk, const float* __restrict__ bk,
    const float* __restrict__ Wv, const float* __restrict__ bv,
    float* __restrict__ outK, float* __restrict__ outV)
{
    extern __shared__ float sm[];
    float* sWp = sm;            /* 704   */
    float* sWr = sWp + 704;     /* 12288 : raw Wq|Wk|Wv */
    float* sfW = sWr + 12288;   /* 2816  : fused x|q|k|v */
    float* sB  = sfW + 2816;    /* 256   : fused biases  */
    float* sBr = sB  + 256;     /* 256   : raw bp|bq|bk|bv */
    float* sIn = sBr + 256;     /* 704   */
    const int tid = threadIdx.x;
    const int row0 = blockIdx.x * 64;

    /* single-pass staging of everything */
    for (int i = tid; i < 704; i += 512) sWp[i] = Wp[i];
    for (int i = tid; i < 4096; i += 512) {
        sWr[i]        = Wq[i];
        sWr[4096 + i] = Wk[i];
        sWr[8192 + i] = Wv[i];
    }
    if (tid < 64) {
        sBr[tid]     = bp[tid];
        sBr[64+tid]  = bq[tid];
        sBr[128+tid] = bk[tid];
        sBr[192+tid] = bv[tid];
    }
    for (int i = tid; i < 704; i += 512) sIn[i] = inp[(size_t)row0*11 + i];
    __syncthreads();

    /* fold: fused x-path + q/k/v paths + biases */
    for (int idx = tid; idx < 704; idx += 512) sfW[idx] = 8.0f * sWp[idx];
    for (int idx = tid; idx < 2112; idx += 512) {
        const int t = idx / 704;            /* 0=q, 1=k, 2=v */
        const int rem = idx - t*704;
        const int i = rem >> 6, j = rem & 63;
        const float fw = (t == 0) ? 1.0f : 8.0f;
        const float* Wc = sWr + t*4096;
        float s = 0.0f;
        #pragma unroll 8
        for (int d = 0; d < 64; ++d) s += sWp[i*64 + d] * Wc[d*64 + j];
        sfW[704 + idx] = fw * s;
    }
    if (tid < 64) {
        sB[tid] = 8.0f * sBr[tid];
    } else if (tid < 256) {
        const int t = (tid >> 6) - 1;       /* 0=q, 1=k, 2=v */
        const int j = tid & 63;
        const float fw = (t == 0) ? 1.0f   : 8.0f;
        const float fb = (t == 0) ? 0.125f : 1.0f;
        const float* Wc = sWr + t*4096;
        float s = 0.0f;
        #pragma unroll 8
        for (int d = 0; d < 64; ++d) s += sBr[d] * Wc[d*64 + j];
        sB[tid] = fw * s + fb * sBr[(t+1)*64 + j];
    }
    __syncthreads();

    /* qkv main (R14 winner body) */
    const int j = tid & 63, rb = (tid >> 6) * 8;
    float wx[11], wq[11], wk[11], wv[11];
    #pragma unroll
    for (int i = 0; i < 11; ++i) {
        wx[i] = sfW[i*64 + j];
        wq[i] = sfW[704  + i*64 + j];
        wk[i] = sfW[1408 + i*64 + j];
        wv[i] = sfW[2112 + i*64 + j];
    }
    float ax[8], aq[8], ak[8], av[8];
    #pragma unroll
    for (int r = 0; r < 8; ++r) {
        ax[r] = sB[j]; aq[r] = sB[64+j]; ak[r] = sB[128+j]; av[r] = sB[192+j];
    }
    #pragma unroll
    for (int i = 0; i < 11; ++i) {
        #pragma unroll
        for (int r = 0; r < 8; ++r) {
            float in = sIn[(rb+r)*11 + i];
            ax[r] += in * wx[i];
            aq[r] += in * wq[i];
            ak[r] += in * wk[i];
            av[r] += in * wv[i];
        }
    }
    #pragma unroll
    for (int r = 0; r < 8; ++r) {
        size_t n = (size_t)(row0 + rb + r) * 64 + j;
        g_x[n]  = ax[r];
        g_q[n]  = aq[r];
        outK[n] = ak[r];
        outV[n] = av[r];
    }
}

/* ------------------------------------------------------------------ */
/* K2: causal attention (R14 winner, verbatim).                       */
/* ------------------------------------------------------------------ */
template<int NC>
__device__ __forceinline__ void score_nc(
    const float* __restrict__ sKt, const float* __restrict__ sQ,
    int mbase, int lane, float (&sc)[5][5])
{
    #pragma unroll 2
    for (int i = 0; i < 64; ++i) {
        float kv[NC];
        #pragma unroll
        for (int c = 0; c < NC; ++c) kv[c] = sKt[i*161 + c*32 + lane];
        #pragma unroll
        for (int k = 0; k < 5; ++k) {
            float qi = sQ[(mbase+k)*64 + i];
            #pragma unroll
            for (int c = 0; c < NC; ++c) sc[k][c] += qi * kv[c];
        }
    }
}

__global__ void __launch_bounds__(256) k_attn(
    const float* __restrict__ Kin, const float* __restrict__ Vin,
    float* __restrict__ attnOut)
{
    extern __shared__ float sm[];
    float* sKt = sm;             /* 64 x 161 = 10304; reused as sA */
    float* sV  = sKt + 10304;    /* 160 x 64 = 10240 */
    float* sQ  = sV  + 10240;    /* 40 x 64  = 2560  */
    float* sA  = sKt;

    const int tid  = threadIdx.x;
    const int lane = tid & 31;
    const int w    = tid >> 5;
    const int part = blockIdx.x >> 2;
    const int quad = blockIdx.x & 3;
    const int r    = (w < 4) ? w : 11 - w;
    const int mbase = 5 * r;
    const int tmax  = quad + 20*r + 16;
    const int nc    = (tmax >> 5) + 1;

    const float4* Kg4 = (const float4*)(Kin + (size_t)part*160*64);
    const float4* Vg4 = (const float4*)(Vin + (size_t)part*160*64);
    float4* sV4 = (float4*)sV;

    for (int idx = tid; idx < 160*16; idx += 256) {
        int s = idx >> 4, i4 = (idx & 15) * 4;
        float4 kk = Kg4[idx];
        sKt[(i4+0)*161 + s] = kk.x;
        sKt[(i4+1)*161 + s] = kk.y;
        sKt[(i4+2)*161 + s] = kk.z;
        sKt[(i4+3)*161 + s] = kk.w;
        sV4[idx] = Vg4[idx];
    }
    for (int idx = tid; idx < 40*16; idx += 256) {
        int m = idx >> 4, i4 = idx & 15;
        int row = part*160 + quad + 4*m;
        ((float4*)(sQ + m*64))[i4] = ((const float4*)(g_q + (size_t)row*64))[i4];
    }
    __syncthreads();

    float sc[5][5];
    #pragma unroll
    for (int k = 0; k < 5; ++k)
        #pragma unroll
        for (int c = 0; c < 5; ++c) sc[k][c] = 0.0f;

    switch (nc) {
        case 1: score_nc<1>(sKt, sQ, mbase, lane, sc); break;
        case 2: score_nc<2>(sKt, sQ, mbase, lane, sc); break;
        case 3: score_nc<3>(sKt, sQ, mbase, lane, sc); break;
        case 4: score_nc<4>(sKt, sQ, mbase, lane, sc); break;
        default: score_nc<5>(sKt, sQ, mbase, lane, sc); break;
    }

    #pragma unroll
    for (int k = 0; k < 5; ++k) {
        const int t = quad + 4*(mbase + k);
        float mval = -3.4e38f;
        #pragma unroll
        for (int c = 0; c < 5; ++c) {
            int s = c*32 + lane;
            if (c < nc && s <= t) mval = fmaxf(mval, sc[k][c]);
        }
        #pragma unroll
        for (int o = 16; o; o >>= 1) mval = fmaxf(mval, __shfl_xor_sync(0xffffffffu, mval, o));
        float sum = 0.0f;
        #pragma unroll
        for (int c = 0; c < 5; ++c) {
            int s = c*32 + lane;
            float p = (c < nc && s <= t) ? expf(sc[k][c] - mval) : 0.0f;
            sc[k][c] = p;
            sum += p;
        }
        #pragma unroll
        for (int o = 16; o; o >>= 1) sum += __shfl_xor_sync(0xffffffffu, sum, o);
        float inv = 1.0f / sum;
        float* arow = attnOut + (size_t)(part*160 + t)*160;
        #pragma unroll
        for (int c = 0; c < 5; ++c) {
            if (c < nc) {
                sc[k][c] *= inv;
                arow[c*32 + lane] = sc[k][c];
            } else {
                arow[c*32 + lane] = 0.0f;
            }
        }
    }

    __syncthreads();

    #pragma unroll
    for (int k = 0; k < 5; ++k) {
        #pragma unroll
        for (int c = 0; c < 5; ++c)
            if (c < nc) sA[(mbase+k)*160 + c*32 + lane] = sc[k][c];
    }
    __syncwarp();

    const float2* sV2 = (const float2*)sV;
    float2 acc[5];
    #pragma unroll
    for (int k = 0; k < 5; ++k) acc[k] = make_float2(0.f, 0.f);

    const int send = (tmax + 4) & ~3;
    for (int s = 0; s < send; s += 4) {
        float4 a[5];
        #pragma unroll
        for (int k = 0; k < 5; ++k)
            a[k] = *(const float4*)(sA + (mbase+k)*160 + s);
        float2 v0 = sV2[(s+0)*32 + lane];
        float2 v1 = sV2[(s+1)*32 + lane];
        float2 v2 = sV2[(s+2)*32 + lane];
        float2 v3 = sV2[(s+3)*32 + lane];
        #pragma unroll
        for (int k = 0; k < 5; ++k) {
            acc[k].x += a[k].x*v0.x + a[k].y*v1.x + a[k].z*v2.x + a[k].w*v3.x;
            acc[k].y += a[k].x*v0.y + a[k].y*v1.y + a[k].z*v2.y + a[k].w*v3.y;
        }
    }
    #pragma unroll
    for (int k = 0; k < 5; ++k) {
        const int t = quad + 4*(mbase + k);
        size_t n = (size_t)part*160 + t;
        ((float2*)(g_z + n*64))[lane] = acc[k];
    }
}

/* ------------------------------------------------------------------ */
/* K3: persistent epilogue (R14 winner, verbatim).                    */
/* ------------------------------------------------------------------ */
__global__ void __launch_bounds__(512) k_epi(
    const float* __restrict__ Wo, const float* __restrict__ bo,
    const float* __restrict__ ln1g, const float* __restrict__ ln1b,
    const float* __restrict__ W1, const float* __restrict__ b1,
    const float* __restrict__ W2, const float* __restrict__ b2,
    const float* __restrict__ ln2g, const float* __restrict__ ln2b,
    const float* __restrict__ Wf, const float* __restrict__ bf,
    float* __restrict__ outR, float* __restrict__ outP, float* __restrict__ outP2)
{
    extern __shared__ float sm[];
    float* sWo = sm;            /* 4096  */
    float* sW1 = sWo + 4096;    /* 16384 */
    float* sW2 = sW1 + 16384;   /* 16384 */
    float* sC  = sW2 + 16384;   /* 704 */
    float* sO1 = sC  + 704;     /* 2048 */
    float* sH  = sO1 + 2048;    /* 8192 (also Wo partials 4x2048) */
    float* sP  = sH  + 8192;    /* 8192: FFN2 partials 4x2048 */

    const int tid = threadIdx.x;

    for (int i = tid; i < 1024; i += 512) ((float4*)sWo)[i] = ((const float4*)Wo)[i];
    for (int i = tid; i < 4096; i += 512) {
        ((float4*)sW1)[i] = ((const float4*)W1)[i];
        ((float4*)sW2)[i] = ((const float4*)W2)[i];
    }
    if (tid < 64) {
        sC[tid]     = bo[tid];
        sC[320+tid] = b2[tid];
        sC[384+tid] = ln1g[tid];
        sC[448+tid] = ln1b[tid];
        sC[512+tid] = ln2g[tid];
        sC[576+tid] = ln2b[tid];
        sC[640+tid] = Wf[tid];
    }
    if (tid < 256) sC[64 + tid] = b1[tid];
    const float bfv = bf[0];
    __syncthreads();

    const int isp = tid >> 7;          /* 0..3 K-split */
    const int t1  = tid & 127;
    const int cq  = t1 & 15;           /* col-quad */
    const int rq  = t1 >> 4;           /* 0..7 -> rows 4rq.. */

    for (int tile = blockIdx.x; tile < NROW/32; tile += gridDim.x) {
        const int row0 = tile * 32;

        /* (1) Wo: 4-way K-split, 4 rows x 4 cols */
        {
            float4 acc0 = {0,0,0,0}, acc1 = {0,0,0,0}, acc2 = {0,0,0,0}, acc3 = {0,0,0,0};
            #pragma unroll
            for (int i4 = isp*4; i4 < isp*4 + 4; ++i4) {
                float4 w0 = ((const float4*)(sWo + (i4*4+0)*64))[cq];
                float4 w1 = ((const float4*)(sWo + (i4*4+1)*64))[cq];
                float4 w2 = ((const float4*)(sWo + (i4*4+2)*64))[cq];
                float4 w3 = ((const float4*)(sWo + (i4*4+3)*64))[cq];
                float4 a0 = ((const float4*)(g_z + (size_t)(row0 + 4*rq+0)*64))[i4];
                float4 a1 = ((const float4*)(g_z + (size_t)(row0 + 4*rq+1)*64))[i4];
                float4 a2 = ((const float4*)(g_z + (size_t)(row0 + 4*rq+2)*64))[i4];
                float4 a3 = ((const float4*)(g_z + (size_t)(row0 + 4*rq+3)*64))[i4];
                fma4(acc0, a0.x, w0); fma4(acc0, a0.y, w1); fma4(acc0, a0.z, w2); fma4(acc0, a0.w, w3);
                fma4(acc1, a1.x, w0); fma4(acc1, a1.y, w1); fma4(acc1, a1.z, w2); fma4(acc1, a1.w, w3);
                fma4(acc2, a2.x, w0); fma4(acc2, a2.y, w1); fma4(acc2, a2.z, w2); fma4(acc2, a2.w, w3);
                fma4(acc3, a3.x, w0); fma4(acc3, a3.y, w1); fma4(acc3, a3.z, w2); fma4(acc3, a3.w, w3);
            }
            float4* dst = (float4*)(sH + isp*2048);
            dst[(4*rq+0)*16 + cq] = acc0;
            dst[(4*rq+1)*16 + cq] = acc1;
            dst[(4*rq+2)*16 + cq] = acc2;
            dst[(4*rq+3)*16 + cq] = acc3;
        }
        __syncthreads();
        /* (2) reduce + bias + residual + LN1 -> sO1 */
        {
            const float4* p = (const float4*)sH;
            float4 v = p[tid];
            float4 v1 = p[512 + tid], v2 = p[1024 + tid], v3 = p[1536 + tid];
            const int row = tid >> 4, c4 = tid & 15;
            float4 b = ((const float4*)sC)[c4];
            float4 rx = ((const float4*)(g_x + (size_t)(row0 + row)*64))[c4];
            v.x += v1.x + v2.x + v3.x + b.x + rx.x;
            v.y += v1.y + v2.y + v3.y + b.y + rx.y;
            v.z += v1.z + v2.z + v3.z + b.z + rx.z;
            v.w += v1.w + v2.w + v3.w + b.w + rx.w;
            float s = v.x + v.y + v.z + v.w;
            #pragma unroll
            for (int o = 8; o; o >>= 1) s += __shfl_xor_sync(0xffffffffu, s, o);
            float mu = s * (1.0f/64.0f);
            float4 d = {v.x-mu, v.y-mu, v.z-mu, v.w-mu};
            float q = d.x*d.x + d.y*d.y + d.z*d.z + d.w*d.w;
            #pragma unroll
            for (int o = 8; o; o >>= 1) q += __shfl_xor_sync(0xffffffffu, q, o);
            float is = rsqrtf(q * (1.0f/64.0f) + 1e-6f);
            float4 g = ((const float4*)(sC + 384))[c4];
            float4 bb = ((const float4*)(sC + 448))[c4];
            float4 o1 = {g.x*d.x*is + bb.x, g.y*d.y*is + bb.y,
                         g.z*d.z*is + bb.z, g.w*d.w*is + bb.w};
            ((float4*)sO1)[tid] = o1;
        }
        __syncthreads();

        /* (3) FFN1 4x4 + relu */
        {
            const int cqf = tid & 63;
            const int rqf = tid >> 6;
            float4 b = ((const float4*)(sC + 64))[cqf];
            float4 acc0 = b, acc1 = b, acc2 = b, acc3 = b;
            #pragma unroll 4
            for (int i4 = 0; i4 < 16; ++i4) {
                float4 w0 = ((const float4*)(sW1 + (i4*4+0)*256))[cqf];
                float4 w1 = ((const float4*)(sW1 + (i4*4+1)*256))[cqf];
                float4 w2 = ((const float4*)(sW1 + (i4*4+2)*256))[cqf];
                float4 w3 = ((const float4*)(sW1 + (i4*4+3)*256))[cqf];
                float4 a0 = ((const float4*)(sO1 + (4*rqf+0)*64))[i4];
                float4 a1 = ((const float4*)(sO1 + (4*rqf+1)*64))[i4];
                float4 a2 = ((const float4*)(sO1 + (4*rqf+2)*64))[i4];
                float4 a3 = ((const float4*)(sO1 + (4*rqf+3)*64))[i4];
                fma4(acc0, a0.x, w0); fma4(acc0, a0.y, w1); fma4(acc0, a0.z, w2); fma4(acc0, a0.w, w3);
                fma4(acc1, a1.x, w0); fma4(acc1, a1.y, w1); fma4(acc1, a1.z, w2); fma4(acc1, a1.w, w3);
                fma4(acc2, a2.x, w0); fma4(acc2, a2.y, w1); fma4(acc2, a2.z, w2); fma4(acc2, a2.w, w3);
                fma4(acc3, a3.x, w0); fma4(acc3, a3.y, w1); fma4(acc3, a3.z, w2); fma4(acc3, a3.w, w3);
            }
            acc0.x = fmaxf(acc0.x, 0.f); acc0.y = fmaxf(acc0.y, 0.f);
            acc0.z = fmaxf(acc0.z, 0.f); acc0.w = fmaxf(acc0.w, 0.f);
            acc1.x = fmaxf(acc1.x, 0.f); acc1.y = fmaxf(acc1.y, 0.f);
            acc1.z = fmaxf(acc1.z, 0.f); acc1.w = fmaxf(acc1.w, 0.f);
            acc2.x = fmaxf(acc2.x, 0.f); acc2.y = fmaxf(acc2.y, 0.f);
            acc2.z = fmaxf(acc2.z, 0.f); acc2.w = fmaxf(acc2.w, 0.f);
            acc3.x = fmaxf(acc3.x, 0.f); acc3.y = fmaxf(acc3.y, 0.f);
            acc3.z = fmaxf(acc3.z, 0.f); acc3.w = fmaxf(acc3.w, 0.f);
            ((float4*)(sH + (4*rqf+0)*256))[cqf] = acc0;
            ((float4*)(sH + (4*rqf+1)*256))[cqf] = acc1;
            ((float4*)(sH + (4*rqf+2)*256))[cqf] = acc2;
            ((float4*)(sH + (4*rqf+3)*256))[cqf] = acc3;
        }
        __syncthreads();

        /* (4) FFN2: 4-way K-split, 4 rows x 4 cols */
        {
            float4 acc0 = {0,0,0,0}, acc1 = {0,0,0,0}, acc2 = {0,0,0,0}, acc3 = {0,0,0,0};
            #pragma unroll 4
            for (int i4 = isp*16; i4 < isp*16 + 16; ++i4) {
                float4 w0 = ((const float4*)(sW2 + (i4*4+0)*64))[cq];
                float4 w1 = ((const float4*)(sW2 + (i4*4+1)*64))[cq];
                float4 w2 = ((const float4*)(sW2 + (i4*4+2)*64))[cq];
                float4 w3 = ((const float4*)(sW2 + (i4*4+3)*64))[cq];
                float4 a0 = ((const float4*)(sH + (4*rq+0)*256))[i4];
                float4 a1 = ((const float4*)(sH + (4*rq+1)*256))[i4];
                float4 a2 = ((const float4*)(sH + (4*rq+2)*256))[i4];
                float4 a3 = ((const float4*)(sH + (4*rq+3)*256))[i4];
                fma4(acc0, a0.x, w0); fma4(acc0, a0.y, w1); fma4(acc0, a0.z, w2); fma4(acc0, a0.w, w3);
                fma4(acc1, a1.x, w0); fma4(acc1, a1.y, w1); fma4(acc1, a1.z, w2); fma4(acc1, a1.w, w3);
                fma4(acc2, a2.x, w0); fma4(acc2, a2.y, w1); fma4(acc2, a2.z, w2); fma4(acc2, a2.w, w3);
                fma4(acc3, a3.x, w0); fma4(acc3, a3.y, w1); fma4(acc3, a3.z, w2); fma4(acc3, a3.w, w3);
            }
            float4* dst = (float4*)(sP + isp*2048);
            dst[(4*rq+0)*16 + cq] = acc0;
            dst[(4*rq+1)*16 + cq] = acc1;
            dst[(4*rq+2)*16 + cq] = acc2;
            dst[(4*rq+3)*16 + cq] = acc3;
        }
        __syncthreads();
        /* (5) reduce 4 + bias + residual + LN2 + outputs */
        {
            const float4* p = (const float4*)sP;
            float4 v = p[tid];
            float4 v1 = p[512 + tid], v2 = p[1024 + tid], v3 = p[1536 + tid];
            const int row = tid >> 4, c4 = tid & 15;
            float4 b = ((const float4*)(sC + 320))[c4];
            float4 rs = ((const float4*)sO1)[tid];
            v.x += v1.x + v2.x + v3.x + b.x + rs.x;
            v.y += v1.y + v2.y + v3.y + b.y + rs.y;
            v.z += v1.z + v2.z + v3.z + b.z + rs.z;
            v.w += v1.w + v2.w + v3.w + b.w + rs.w;
            float s = v.x + v.y + v.z + v.w;
            #pragma unroll
            for (int o = 8; o; o >>= 1) s += __shfl_xor_sync(0xffffffffu, s, o);
            float mu = s * (1.0f/64.0f);
            float4 d = {v.x-mu, v.y-mu, v.z-mu, v.w-mu};
            float q = d.x*d.x + d.y*d.y + d.z*d.z + d.w*d.w;
            #pragma unroll
            for (int o = 8; o; o >>= 1) q += __shfl_xor_sync(0xffffffffu, q, o);
            float is = rsqrtf(q * (1.0f/64.0f) + 1e-6f);
            float4 g = ((const float4*)(sC + 512))[c4];
            float4 bb = ((const float4*)(sC + 576))[c4];
            float4 rv = {g.x*d.x*is + bb.x, g.y*d.y*is + bb.y,
                         g.z*d.z*is + bb.z, g.w*d.w*is + bb.w};
            const size_t n = (size_t)row0 + row;
            ((float4*)(outR + n*64))[c4] = rv;
            float4 wf = ((const float4*)(sC + 640))[c4];
            float pp = rv.x*wf.x + rv.y*wf.y + rv.z*wf.z + rv.w*wf.w;
            #pragma unroll
            for (int o = 8; o; o >>= 1) pp += __shfl_xor_sync(0xffffffffu, pp, o);
            if (c4 == 0) {
                float pv = pp + bfv;
                outP[n]  = pv;
                outP2[n] = pv;
            }
        }
        __syncthreads();
    }
}

/* ------------------------------------------------------------------ */
extern "C" void kernel_launch(void* const* d_in, const int* in_sizes, int n_in,
                              void* d_out, int out_size)
{
    (void)in_sizes; (void)n_in; (void)out_size;
    const float* inputs = (const float*)d_in[0];
    const float* Wp  = (const float*)d_in[2];
    const float* bp  = (const float*)d_in[3];
    const float* Wq  = (const float*)d_in[4];
    const float* bq  = (const float*)d_in[5];
    const float* Wk  = (const float*)d_in[6];
    const float* bk  = (const float*)d_in[7];
    const float* Wv  = (const float*)d_in[8];
    const float* bv  = (const float*)d_in[9];
    const float* Wo  = (const float*)d_in[10];
    const float* bo  = (const float*)d_in[11];
    const float* l1g = (const float*)d_in[12];
    const float* l1b = (const float*)d_in[13];
    const float* W1  = (const float*)d_in[14];
    const float* b1  = (const float*)d_in[15];
    const float* W2  = (const float*)d_in[16];
    const float* b2  = (const float*)d_in[17];
    const float* l2g = (const float*)d_in[18];
    const float* l2b = (const float*)d_in[19];
    const float* Wf  = (const float*)d_in[20];
    const float* bf  = (const float*)d_in[21];
    float* out = (float*)d_out;

    const size_t sm1 = (size_t)(704 + 12288 + 2816 + 256 + 256 + 704) * 4;      /* ~67 KB  */
    const size_t sm2 = (size_t)(10304 + 10240 + 2560) * 4;                      /* ~92 KB  */
    const size_t sm3 = (size_t)(4096 + 16384 + 16384 + 704 + 2048 + 8192 + 8192) * 4; /* ~219 KB */

    cudaFuncSetAttribute(k_qkv,  cudaFuncAttributeMaxDynamicSharedMemorySize, (int)sm1);
    cudaFuncSetAttribute(k_attn, cudaFuncAttributeMaxDynamicSharedMemorySize, (int)sm2);
    cudaFuncSetAttribute(k_epi,  cudaFuncAttributeMaxDynamicSharedMemorySize, (int)sm3);

    k_qkv<<<NROW/64, 512, sm1>>>(inputs, Wp, bp, Wq, bq, Wk, bk, Wv, bv,
                                 out + OFF_K, out + OFF_V);
    k_attn<<<NPART*4, 256, sm2>>>(out + OFF_K, out + OFF_V, out + OFF_ATTN);
    k_epi<<<148, 512, sm3>>>(Wo, bo, l1g, l1b, W1, b1, W2, b2, l2g, l2b, Wf, bf,
                             out + OFF_R, out + OFF_PRED, out + OFF_PRED2);
}

// round 17
// speedup vs baseline: 1.0520x; 1.0520x over previous
#include <cuda_runtime.h>

#define B_ 8
#define P_ 10
#define S_ 160
#define FX_ 11
#define D_ 64
#define DFF_ 256
#define NROW (B_*P_*S_)   /* 12800 */
#define NPART (B_*P_)     /* 80 */

/* output layout (tuple order): pred, pred_resampl, K, V, R, attn_weights */
#define OFF_PRED  0
#define OFF_PRED2 (NROW)
#define OFF_K     (2*NROW)
#define OFF_V     (OFF_K + NROW*D_)
#define OFF_R     (OFF_V + NROW*D_)
#define OFF_ATTN  (OFF_R + NROW*D_)

/* scratch (no cudaMalloc allowed) */
__device__ float g_x[NROW*D_];
__device__ float g_q[NROW*D_];
__device__ float g_z[NROW*D_];
__device__ float g_fw[4*704];   /* fused 11x64 weights: x,q,k,v */
__device__ float g_fb[4*64];    /* fused biases */

__device__ __forceinline__ void fma4(float4& acc, float s, const float4& v) {
    acc.x += s * v.x; acc.y += s * v.y; acc.z += s * v.z; acc.w += s * v.w;
}

/* ------------------------------------------------------------------ */
/* K0: fold Wp into Wq/Wk/Wv. WIDE: 134 blocks.                       */
/*   b in [0,132): one (type, row, 16-col quarter); 16-way K-split    */
/*   b=132: x-path copy; b=133: fused biases.                         */
/* Attention scale 1/8 folded into Wq path.                           */
/* ------------------------------------------------------------------ */
__global__ void __launch_bounds__(256) k_fold(
    const float* __restrict__ Wp, const float* __restrict__ bp,
    const float* __restrict__ Wq, const float* __restrict__ bq,
    const float* __restrict__ Wk, const float* __restrict__ bk,
    const float* __restrict__ Wv, const float* __restrict__ bv)
{
    __shared__ float red[256];
    const int b = blockIdx.x, tid = threadIdx.x;

    if (b == 132) {
        for (int i = tid; i < 704; i += 256) g_fw[i] = 8.0f * Wp[i];
        if (tid < 64) g_fb[tid] = 8.0f * bp[tid];
        return;
    }
    if (b == 133) {
        const int j = tid & 63, p = tid >> 6;
        #pragma unroll
        for (int t = 1; t <= 3; ++t) {
            const float* W  = (t == 1) ? Wq : (t == 2) ? Wk : Wv;
            const float* bb = (t == 1) ? bq : (t == 2) ? bk : bv;
            const float fw  = (t == 1) ? 1.0f   : 8.0f;
            const float fb  = (t == 1) ? 0.125f : 1.0f;
            float s = 0.0f;
            #pragma unroll
            for (int d = p*16; d < p*16 + 16; ++d)
                s += bp[d] * W[d*64 + j];
            red[tid] = s;
            __syncthreads();
            if (p == 0)
                g_fb[t*64 + j] =
                    fw * (red[j] + red[64+j] + red[128+j] + red[192+j]) + fb * bb[j];
            __syncthreads();
        }
        return;
    }

    /* compute blocks: b -> (t, i, jq) */
    const int t   = b / 44;            /* 0=q, 1=k, 2=v */
    const int rem = b % 44;
    const int i   = rem >> 2;          /* 0..10 */
    const int jq  = rem & 3;           /* 16-col quarter */
    const float* W  = (t == 0) ? Wq : (t == 1) ? Wk : Wv;
    const float fw  = (t == 0) ? 1.0f : 8.0f;

    const int l = tid & 15;            /* col within quarter */
    const int p = tid >> 4;            /* 0..15 K-split */
    const int j = jq*16 + l;
    float s = 0.0f;
    #pragma unroll
    for (int d = p*4; d < p*4 + 4; ++d)
        s += Wp[i*64 + d] * W[d*64 + j];
    red[tid] = s;
    __syncthreads();
    if (p == 0) {
        float acc = 0.0f;
        #pragma unroll
        for (int pp = 0; pp < 16; ++pp) acc += red[pp*16 + l];
        g_fw[(t+1)*704 + i*64 + j] = fw * acc;
    }
}

/* ------------------------------------------------------------------ */
/* K1: x,q,k,v = in @ fused.  512 thr, 64 rows/block, weights in regs */
/* ------------------------------------------------------------------ */
__global__ void __launch_bounds__(512) k_qkv(
    const float* __restrict__ inp,
    float* __restrict__ outK, float* __restrict__ outV)
{
    extern __shared__ float sm[];
    float* sW  = sm;          /* 2816 */
    float* sB  = sW + 2816;   /* 256  */
    float* sIn = sB + 256;    /* 704  */
    const int tid = threadIdx.x;
    const int row0 = blockIdx.x * 64;

    for (int i = tid; i < 2816; i += 512) sW[i] = g_fw[i];
    if (tid < 256) sB[tid] = g_fb[tid];
    for (int i = tid; i < 704; i += 512) sIn[i] = inp[(size_t)row0*11 + i];
    __syncthreads();

    const int j = tid & 63, rb = (tid >> 6) * 8;
    float wx[11], wq[11], wk[11], wv[11];
    #pragma unroll
    for (int i = 0; i < 11; ++i) {
        wx[i] = sW[i*64 + j];
        wq[i] = sW[704  + i*64 + j];
        wk[i] = sW[1408 + i*64 + j];
        wv[i] = sW[2112 + i*64 + j];
    }
    float ax[8], aq[8], ak[8], av[8];
    #pragma unroll
    for (int r = 0; r < 8; ++r) {
        ax[r] = sB[j]; aq[r] = sB[64+j]; ak[r] = sB[128+j]; av[r] = sB[192+j];
    }
    #pragma unroll
    for (int i = 0; i < 11; ++i) {
        #pragma unroll
        for (int r = 0; r < 8; ++r) {
            float in = sIn[(rb+r)*11 + i];
            ax[r] += in * wx[i];
            aq[r] += in * wq[i];
            ak[r] += in * wk[i];
            av[r] += in * wv[i];
        }
    }
    #pragma unroll
    for (int r = 0; r < 8; ++r) {
        size_t n = (size_t)(row0 + rb + r) * 64 + j;
        g_x[n]  = ax[r];
        g_q[n]  = aq[r];
        outK[n] = ak[r];
        outV[n] = av[r];
    }
}

/* ------------------------------------------------------------------ */
/* K2: causal attention (R14 winner, verbatim).                       */
/* ------------------------------------------------------------------ */
template<int NC>
__device__ __forceinline__ void score_nc(
    const float* __restrict__ sKt, const float* __restrict__ sQ,
    int mbase, int lane, float (&sc)[5][5])
{
    #pragma unroll 2
    for (int i = 0; i < 64; ++i) {
        float kv[NC];
        #pragma unroll
        for (int c = 0; c < NC; ++c) kv[c] = sKt[i*161 + c*32 + lane];
        #pragma unroll
        for (int k = 0; k < 5; ++k) {
            float qi = sQ[(mbase+k)*64 + i];
            #pragma unroll
            for (int c = 0; c < NC; ++c) sc[k][c] += qi * kv[c];
        }
    }
}

__global__ void __launch_bounds__(256) k_attn(
    const float* __restrict__ Kin, const float* __restrict__ Vin,
    float* __restrict__ attnOut)
{
    extern __shared__ float sm[];
    float* sKt = sm;             /* 64 x 161 = 10304; reused as sA */
    float* sV  = sKt + 10304;    /* 160 x 64 = 10240 */
    float* sQ  = sV  + 10240;    /* 40 x 64  = 2560  */
    float* sA  = sKt;

    const int tid  = threadIdx.x;
    const int lane = tid & 31;
    const int w    = tid >> 5;
    const int part = blockIdx.x >> 2;
    const int quad = blockIdx.x & 3;
    const int r    = (w < 4) ? w : 11 - w;
    const int mbase = 5 * r;
    const int tmax  = quad + 20*r + 16;
    const int nc    = (tmax >> 5) + 1;

    const float4* Kg4 = (const float4*)(Kin + (size_t)part*160*64);
    const float4* Vg4 = (const float4*)(Vin + (size_t)part*160*64);
    float4* sV4 = (float4*)sV;

    for (int idx = tid; idx < 160*16; idx += 256) {
        int s = idx >> 4, i4 = (idx & 15) * 4;
        float4 kk = Kg4[idx];
        sKt[(i4+0)*161 + s] = kk.x;
        sKt[(i4+1)*161 + s] = kk.y;
        sKt[(i4+2)*161 + s] = kk.z;
        sKt[(i4+3)*161 + s] = kk.w;
        sV4[idx] = Vg4[idx];
    }
    for (int idx = tid; idx < 40*16; idx += 256) {
        int m = idx >> 4, i4 = idx & 15;
        int row = part*160 + quad + 4*m;
        ((float4*)(sQ + m*64))[i4] = ((const float4*)(g_q + (size_t)row*64))[i4];
    }
    __syncthreads();

    float sc[5][5];
    #pragma unroll
    for (int k = 0; k < 5; ++k)
        #pragma unroll
        for (int c = 0; c < 5; ++c) sc[k][c] = 0.0f;

    switch (nc) {
        case 1: score_nc<1>(sKt, sQ, mbase, lane, sc); break;
        case 2: score_nc<2>(sKt, sQ, mbase, lane, sc); break;
        case 3: score_nc<3>(sKt, sQ, mbase, lane, sc); break;
        case 4: score_nc<4>(sKt, sQ, mbase, lane, sc); break;
        default: score_nc<5>(sKt, sQ, mbase, lane, sc); break;
    }

    #pragma unroll
    for (int k = 0; k < 5; ++k) {
        const int t = quad + 4*(mbase + k);
        float mval = -3.4e38f;
        #pragma unroll
        for (int c = 0; c < 5; ++c) {
            int s = c*32 + lane;
            if (c < nc && s <= t) mval = fmaxf(mval, sc[k][c]);
        }
        #pragma unroll
        for (int o = 16; o; o >>= 1) mval = fmaxf(mval, __shfl_xor_sync(0xffffffffu, mval, o));
        float sum = 0.0f;
        #pragma unroll
        for (int c = 0; c < 5; ++c) {
            int s = c*32 + lane;
            float p = (c < nc && s <= t) ? expf(sc[k][c] - mval) : 0.0f;
            sc[k][c] = p;
            sum += p;
        }
        #pragma unroll
        for (int o = 16; o; o >>= 1) sum += __shfl_xor_sync(0xffffffffu, sum, o);
        float inv = 1.0f / sum;
        float* arow = attnOut + (size_t)(part*160 + t)*160;
        #pragma unroll
        for (int c = 0; c < 5; ++c) {
            if (c < nc) {
                sc[k][c] *= inv;
                arow[c*32 + lane] = sc[k][c];
            } else {
                arow[c*32 + lane] = 0.0f;
            }
        }
    }

    __syncthreads();

    #pragma unroll
    for (int k = 0; k < 5; ++k) {
        #pragma unroll
        for (int c = 0; c < 5; ++c)
            if (c < nc) sA[(mbase+k)*160 + c*32 + lane] = sc[k][c];
    }
    __syncwarp();

    const float2* sV2 = (const float2*)sV;
    float2 acc[5];
    #pragma unroll
    for (int k = 0; k < 5; ++k) acc[k] = make_float2(0.f, 0.f);

    const int send = (tmax + 4) & ~3;
    for (int s = 0; s < send; s += 4) {
        float4 a[5];
        #pragma unroll
        for (int k = 0; k < 5; ++k)
            a[k] = *(const float4*)(sA + (mbase+k)*160 + s);
        float2 v0 = sV2[(s+0)*32 + lane];
        float2 v1 = sV2[(s+1)*32 + lane];
        float2 v2 = sV2[(s+2)*32 + lane];
        float2 v3 = sV2[(s+3)*32 + lane];
        #pragma unroll
        for (int k = 0; k < 5; ++k) {
            acc[k].x += a[k].x*v0.x + a[k].y*v1.x + a[k].z*v2.x + a[k].w*v3.x;
            acc[k].y += a[k].x*v0.y + a[k].y*v1.y + a[k].z*v2.y + a[k].w*v3.y;
        }
    }
    #pragma unroll
    for (int k = 0; k < 5; ++k) {
        const int t = quad + 4*(mbase + k);
        size_t n = (size_t)part*160 + t;
        ((float2*)(g_z + n*64))[lane] = acc[k];
    }
}

/* ------------------------------------------------------------------ */
/* K3: persistent epilogue (R14 winner, verbatim).                    */
/* ------------------------------------------------------------------ */
__global__ void __launch_bounds__(512) k_epi(
    const float* __restrict__ Wo, const float* __restrict__ bo,
    const float* __restrict__ ln1g, const float* __restrict__ ln1b,
    const float* __restrict__ W1, const float* __restrict__ b1,
    const float* __restrict__ W2, const float* __restrict__ b2,
    const float* __restrict__ ln2g, const float* __restrict__ ln2b,
    const float* __restrict__ Wf, const float* __restrict__ bf,
    float* __restrict__ outR, float* __restrict__ outP, float* __restrict__ outP2)
{
    extern __shared__ float sm[];
    float* sWo = sm;            /* 4096  */
    float* sW1 = sWo + 4096;    /* 16384 */
    float* sW2 = sW1 + 16384;   /* 16384 */
    float* sC  = sW2 + 16384;   /* 704 */
    float* sO1 = sC  + 704;     /* 2048 */
    float* sH  = sO1 + 2048;    /* 8192 (also Wo partials 4x2048) */
    float* sP  = sH  + 8192;    /* 8192: FFN2 partials 4x2048 */

    const int tid = threadIdx.x;

    for (int i = tid; i < 1024; i += 512) ((float4*)sWo)[i] = ((const float4*)Wo)[i];
    for (int i = tid; i < 4096; i += 512) {
        ((float4*)sW1)[i] = ((const float4*)W1)[i];
        ((float4*)sW2)[i] = ((const float4*)W2)[i];
    }
    if (tid < 64) {
        sC[tid]     = bo[tid];
        sC[320+tid] = b2[tid];
        sC[384+tid] = ln1g[tid];
        sC[448+tid] = ln1b[tid];
        sC[512+tid] = ln2g[tid];
        sC[576+tid] = ln2b[tid];
        sC[640+tid] = Wf[tid];
    }
    if (tid < 256) sC[64 + tid] = b1[tid];
    const float bfv = bf[0];
    __syncthreads();

    const int isp = tid >> 7;          /* 0..3 K-split */
    const int t1  = tid & 127;
    const int cq  = t1 & 15;           /* col-quad */
    const int rq  = t1 >> 4;           /* 0..7 -> rows 4rq.. */

    for (int tile = blockIdx.x; tile < NROW/32; tile += gridDim.x) {
        const int row0 = tile * 32;

        /* (1) Wo: 4-way K-split, 4 rows x 4 cols */
        {
            float4 acc0 = {0,0,0,0}, acc1 = {0,0,0,0}, acc2 = {0,0,0,0}, acc3 = {0,0,0,0};
            #pragma unroll
            for (int i4 = isp*4; i4 < isp*4 + 4; ++i4) {
                float4 w0 = ((const float4*)(sWo + (i4*4+0)*64))[cq];
                float4 w1 = ((const float4*)(sWo + (i4*4+1)*64))[cq];
                float4 w2 = ((const float4*)(sWo + (i4*4+2)*64))[cq];
                float4 w3 = ((const float4*)(sWo + (i4*4+3)*64))[cq];
                float4 a0 = ((const float4*)(g_z + (size_t)(row0 + 4*rq+0)*64))[i4];
                float4 a1 = ((const float4*)(g_z + (size_t)(row0 + 4*rq+1)*64))[i4];
                float4 a2 = ((const float4*)(g_z + (size_t)(row0 + 4*rq+2)*64))[i4];
                float4 a3 = ((const float4*)(g_z + (size_t)(row0 + 4*rq+3)*64))[i4];
                fma4(acc0, a0.x, w0); fma4(acc0, a0.y, w1); fma4(acc0, a0.z, w2); fma4(acc0, a0.w, w3);
                fma4(acc1, a1.x, w0); fma4(acc1, a1.y, w1); fma4(acc1, a1.z, w2); fma4(acc1, a1.w, w3);
                fma4(acc2, a2.x, w0); fma4(acc2, a2.y, w1); fma4(acc2, a2.z, w2); fma4(acc2, a2.w, w3);
                fma4(acc3, a3.x, w0); fma4(acc3, a3.y, w1); fma4(acc3, a3.z, w2); fma4(acc3, a3.w, w3);
            }
            float4* dst = (float4*)(sH + isp*2048);
            dst[(4*rq+0)*16 + cq] = acc0;
            dst[(4*rq+1)*16 + cq] = acc1;
            dst[(4*rq+2)*16 + cq] = acc2;
            dst[(4*rq+3)*16 + cq] = acc3;
        }
        __syncthreads();
        /* (2) reduce + bias + residual + LN1 -> sO1 */
        {
            const float4* p = (const float4*)sH;
            float4 v = p[tid];
            float4 v1 = p[512 + tid], v2 = p[1024 + tid], v3 = p[1536 + tid];
            const int row = tid >> 4, c4 = tid & 15;
            float4 b = ((const float4*)sC)[c4];
            float4 rx = ((const float4*)(g_x + (size_t)(row0 + row)*64))[c4];
            v.x += v1.x + v2.x + v3.x + b.x + rx.x;
            v.y += v1.y + v2.y + v3.y + b.y + rx.y;
            v.z += v1.z + v2.z + v3.z + b.z + rx.z;
            v.w += v1.w + v2.w + v3.w + b.w + rx.w;
            float s = v.x + v.y + v.z + v.w;
            #pragma unroll
            for (int o = 8; o; o >>= 1) s += __shfl_xor_sync(0xffffffffu, s, o);
            float mu = s * (1.0f/64.0f);
            float4 d = {v.x-mu, v.y-mu, v.z-mu, v.w-mu};
            float q = d.x*d.x + d.y*d.y + d.z*d.z + d.w*d.w;
            #pragma unroll
            for (int o = 8; o; o >>= 1) q += __shfl_xor_sync(0xffffffffu, q, o);
            float is = rsqrtf(q * (1.0f/64.0f) + 1e-6f);
            float4 g = ((const float4*)(sC + 384))[c4];
            float4 bb = ((const float4*)(sC + 448))[c4];
            float4 o1 = {g.x*d.x*is + bb.x, g.y*d.y*is + bb.y,
                         g.z*d.z*is + bb.z, g.w*d.w*is + bb.w};
            ((float4*)sO1)[tid] = o1;
        }
        __syncthreads();

        /* (3) FFN1 4x4 + relu */
        {
            const int cqf = tid & 63;
            const int rqf = tid >> 6;
            float4 b = ((const float4*)(sC + 64))[cqf];
            float4 acc0 = b, acc1 = b, acc2 = b, acc3 = b;
            #pragma unroll 4
            for (int i4 = 0; i4 < 16; ++i4) {
                float4 w0 = ((const float4*)(sW1 + (i4*4+0)*256))[cqf];
                float4 w1 = ((const float4*)(sW1 + (i4*4+1)*256))[cqf];
                float4 w2 = ((const float4*)(sW1 + (i4*4+2)*256))[cqf];
                float4 w3 = ((const float4*)(sW1 + (i4*4+3)*256))[cqf];
                float4 a0 = ((const float4*)(sO1 + (4*rqf+0)*64))[i4];
                float4 a1 = ((const float4*)(sO1 + (4*rqf+1)*64))[i4];
                float4 a2 = ((const float4*)(sO1 + (4*rqf+2)*64))[i4];
                float4 a3 = ((const float4*)(sO1 + (4*rqf+3)*64))[i4];
                fma4(acc0, a0.x, w0); fma4(acc0, a0.y, w1); fma4(acc0, a0.z, w2); fma4(acc0, a0.w, w3);
                fma4(acc1, a1.x, w0); fma4(acc1, a1.y, w1); fma4(acc1, a1.z, w2); fma4(acc1, a1.w, w3);
                fma4(acc2, a2.x, w0); fma4(acc2, a2.y, w1); fma4(acc2, a2.z, w2); fma4(acc2, a2.w, w3);
                fma4(acc3, a3.x, w0); fma4(acc3, a3.y, w1); fma4(acc3, a3.z, w2); fma4(acc3, a3.w, w3);
            }
            acc0.x = fmaxf(acc0.x, 0.f); acc0.y = fmaxf(acc0.y, 0.f);
            acc0.z = fmaxf(acc0.z, 0.f); acc0.w = fmaxf(acc0.w, 0.f);
            acc1.x = fmaxf(acc1.x, 0.f); acc1.y = fmaxf(acc1.y, 0.f);
            acc1.z = fmaxf(acc1.z, 0.f); acc1.w = fmaxf(acc1.w, 0.f);
            acc2.x = fmaxf(acc2.x, 0.f); acc2.y = fmaxf(acc2.y, 0.f);
            acc2.z = fmaxf(acc2.z, 0.f); acc2.w = fmaxf(acc2.w, 0.f);
            acc3.x = fmaxf(acc3.x, 0.f); acc3.y = fmaxf(acc3.y, 0.f);
            acc3.z = fmaxf(acc3.z, 0.f); acc3.w = fmaxf(acc3.w, 0.f);
            ((float4*)(sH + (4*rqf+0)*256))[cqf] = acc0;
            ((float4*)(sH + (4*rqf+1)*256))[cqf] = acc1;
            ((float4*)(sH + (4*rqf+2)*256))[cqf] = acc2;
            ((float4*)(sH + (4*rqf+3)*256))[cqf] = acc3;
        }
        __syncthreads();

        /* (4) FFN2: 4-way K-split, 4 rows x 4 cols */
        {
            float4 acc0 = {0,0,0,0}, acc1 = {0,0,0,0}, acc2 = {0,0,0,0}, acc3 = {0,0,0,0};
            #pragma unroll 4
            for (int i4 = isp*16; i4 < isp*16 + 16; ++i4) {
                float4 w0 = ((const float4*)(sW2 + (i4*4+0)*64))[cq];
                float4 w1 = ((const float4*)(sW2 + (i4*4+1)*64))[cq];
                float4 w2 = ((const float4*)(sW2 + (i4*4+2)*64))[cq];
                float4 w3 = ((const float4*)(sW2 + (i4*4+3)*64))[cq];
                float4 a0 = ((const float4*)(sH + (4*rq+0)*256))[i4];
                float4 a1 = ((const float4*)(sH + (4*rq+1)*256))[i4];
                float4 a2 = ((const float4*)(sH + (4*rq+2)*256))[i4];
                float4 a3 = ((const float4*)(sH + (4*rq+3)*256))[i4];
                fma4(acc0, a0.x, w0); fma4(acc0, a0.y, w1); fma4(acc0, a0.z, w2); fma4(acc0, a0.w, w3);
                fma4(acc1, a1.x, w0); fma4(acc1, a1.y, w1); fma4(acc1, a1.z, w2); fma4(acc1, a1.w, w3);
                fma4(acc2, a2.x, w0); fma4(acc2, a2.y, w1); fma4(acc2, a2.z, w2); fma4(acc2, a2.w, w3);
                fma4(acc3, a3.x, w0); fma4(acc3, a3.y, w1); fma4(acc3, a3.z, w2); fma4(acc3, a3.w, w3);
            }
            float4* dst = (float4*)(sP + isp*2048);
            dst[(4*rq+0)*16 + cq] = acc0;
            dst[(4*rq+1)*16 + cq] = acc1;
            dst[(4*rq+2)*16 + cq] = acc2;
            dst[(4*rq+3)*16 + cq] = acc3;
        }
        __syncthreads();
        /* (5) reduce 4 + bias + residual + LN2 + outputs */
        {
            const float4* p = (const float4*)sP;
            float4 v = p[tid];
            float4 v1 = p[512 + tid], v2 = p[1024 + tid], v3 = p[1536 + tid];
            const int row = tid >> 4, c4 = tid & 15;
            float4 b = ((const float4*)(sC + 320))[c4];
            float4 rs = ((const float4*)sO1)[tid];
            v.x += v1.x + v2.x + v3.x + b.x + rs.x;
            v.y += v1.y + v2.y + v3.y + b.y + rs.y;
            v.z += v1.z + v2.z + v3.z + b.z + rs.z;
            v.w += v1.w + v2.w + v3.w + b.w + rs.w;
            float s = v.x + v.y + v.z + v.w;
            #pragma unroll
            for (int o = 8; o; o >>= 1) s += __shfl_xor_sync(0xffffffffu, s, o);
            float mu = s * (1.0f/64.0f);
            float4 d = {v.x-mu, v.y-mu, v.z-mu, v.w-mu};
            float q = d.x*d.x + d.y*d.y + d.z*d.z + d.w*d.w;
            #pragma unroll
            for (int o = 8; o; o >>= 1) q += __shfl_xor_sync(0xffffffffu, q, o);
            float is = rsqrtf(q * (1.0f/64.0f) + 1e-6f);
            float4 g = ((const float4*)(sC + 512))[c4];
            float4 bb = ((const float4*)(sC + 576))[c4];
            float4 rv = {g.x*d.x*is + bb.x, g.y*d.y*is + bb.y,
                         g.z*d.z*is + bb.z, g.w*d.w*is + bb.w};
            const size_t n = (size_t)row0 + row;
            ((float4*)(outR + n*64))[c4] = rv;
            float4 wf = ((const float4*)(sC + 640))[c4];
            float pp = rv.x*wf.x + rv.y*wf.y + rv.z*wf.z + rv.w*wf.w;
            #pragma unroll
            for (int o = 8; o; o >>= 1) pp += __shfl_xor_sync(0xffffffffu, pp, o);
            if (c4 == 0) {
                float pv = pp + bfv;
                outP[n]  = pv;
                outP2[n] = pv;
            }
        }
        __syncthreads();
    }
}

/* ------------------------------------------------------------------ */
extern "C" void kernel_launch(void* const* d_in, const int* in_sizes, int n_in,
                              void* d_out, int out_size)
{
    (void)in_sizes; (void)n_in; (void)out_size;
    const float* inputs = (const float*)d_in[0];
    const float* Wp  = (const float*)d_in[2];
    const float* bp  = (const float*)d_in[3];
    const float* Wq  = (const float*)d_in[4];
    const float* bq  = (const float*)d_in[5];
    const float* Wk  = (const float*)d_in[6];
    const float* bk  = (const float*)d_in[7];
    const float* Wv  = (const float*)d_in[8];
    const float* bv  = (const float*)d_in[9];
    const float* Wo  = (const float*)d_in[10];
    const float* bo  = (const float*)d_in[11];
    const float* l1g = (const float*)d_in[12];
    const float* l1b = (const float*)d_in[13];
    const float* W1  = (const float*)d_in[14];
    const float* b1  = (const float*)d_in[15];
    const float* W2  = (const float*)d_in[16];
    const float* b2  = (const float*)d_in[17];
    const float* l2g = (const float*)d_in[18];
    const float* l2b = (const float*)d_in[19];
    const float* Wf  = (const float*)d_in[20];
    const float* bf  = (const float*)d_in[21];
    float* out = (float*)d_out;

    const size_t sm1 = (size_t)(2816 + 256 + 704) * 4;                          /* ~15 KB  */
    const size_t sm2 = (size_t)(10304 + 10240 + 2560) * 4;                      /* ~92 KB  */
    const size_t sm3 = (size_t)(4096 + 16384 + 16384 + 704 + 2048 + 8192 + 8192) * 4; /* ~219 KB */

    cudaFuncSetAttribute(k_qkv,  cudaFuncAttributeMaxDynamicSharedMemorySize, (int)sm1);
    cudaFuncSetAttribute(k_attn, cudaFuncAttributeMaxDynamicSharedMemorySize, (int)sm2);
    cudaFuncSetAttribute(k_epi,  cudaFuncAttributeMaxDynamicSharedMemorySize, (int)sm3);

    k_fold<<<134, 256>>>(Wp, bp, Wq, bq, Wk, bk, Wv, bv);
    k_qkv<<<NROW/64, 512, sm1>>>(inputs, out + OFF_K, out + OFF_V);
    k_attn<<<NPART*4, 256, sm2>>>(out + OFF_K, out + OFF_V, out + OFF_ATTN);
    k_epi<<<148, 512, sm3>>>(Wo, bo, l1g, l1b, W1, b1, W2, b2, l2g, l2b, Wf, bf,
                             out + OFF_R, out + OFF_PRED, out + OFF_PRED2);
}